// round 1
// baseline (speedup 1.0000x reference)
#include <cuda_runtime.h>
#include <cstdint>

#define N_IMG 16
#define C_IN  256
#define H_IN  128
#define W_IN  128
#define HB    129
#define WB    129
#define C_OUT 512

// Scratch: blurred (and 1/48-prescaled) activations, NCHW [16,256,129,129]
__device__ float g_blur[(size_t)N_IMG * C_IN * HB * WB];

// ---------------------------------------------------------------------------
// Kernel 1: separable 4x4 blur, pad (2,2), output 129x129, prescaled by 1/48.
// blur_k is rank-1 (outer(k,k)/sum), so row sums give the vertical factor and
// col sums the horizontal factor exactly (and this is flip-safe).
// ---------------------------------------------------------------------------
#define CHUNK 26

__global__ void __launch_bounds__(256) blur_kernel(const float* __restrict__ x,
                                                   const float* __restrict__ bk) {
  const int nc = blockIdx.x;            // n*256 + c
  const int r0 = blockIdx.y * CHUNK;    // first output row of this chunk
  const int cnt = min(CHUNK, HB - r0);
  const int t = threadIdx.x;

  __shared__ float sx[CHUNK + 3][W_IN];     // input rows r0-2 .. r0+cnt
  __shared__ float sh[CHUNK + 3][WB + 3];   // horizontally blurred rows
  __shared__ float vco[4], wco[4];

  if (t < 8) {
    const int i = t & 3;
    float s = 0.f;
    if (t < 4) { for (int j = 0; j < 4; ++j) s += bk[i * 4 + j]; vco[i] = s; }
    else       { for (int j = 0; j < 4; ++j) s += bk[j * 4 + i]; wco[i] = s; }
  }

  const int nrows = cnt + 3;
  const float* xb = x + (size_t)nc * (H_IN * W_IN);
  for (int idx = t; idx < nrows * W_IN; idx += 256) {
    const int l = idx >> 7, col = idx & 127;
    const int gr = r0 - 2 + l;
    sx[l][col] = (gr >= 0 && gr < H_IN) ? xb[gr * W_IN + col] : 0.f;
  }
  __syncthreads();

  for (int idx = t; idx < nrows * WB; idx += 256) {
    const int l = idx / WB, ow = idx - l * WB;
    float s = 0.f;
#pragma unroll
    for (int j = 0; j < 4; ++j) {
      const int cc = ow - 2 + j;
      if (cc >= 0 && cc < W_IN) s += wco[j] * sx[l][cc];
    }
    sh[l][ow] = s;
  }
  __syncthreads();

  float* ob = g_blur + (size_t)nc * (HB * WB);
  for (int idx = t; idx < cnt * WB; idx += 256) {
    const int lr = idx / WB, ow = idx - lr * WB;
    float s = 0.f;
#pragma unroll
    for (int i = 0; i < 4; ++i) s += vco[i] * sh[lr + i][ow];
    // fold EqualizedLR weight scale 1/sqrt(256*9) = 1/48 into the activations
    ob[(r0 + lr) * WB + ow] = s * 0.020833333333333332f;
  }
}

// ---------------------------------------------------------------------------
// Kernel 2: 3x3 stride-2 conv on the 129x129 blurred tensor.
// Block: 128 output channels x (8x8 output pixels). 256 threads, each owning
// 4 spatial x 8 oc accumulators as 16 packed f32x2 pairs (fma.rn.f32x2 is the
// Blackwell dual-rate FP32 path; plain FFMA-3reg is half rate).
// ---------------------------------------------------------------------------
__device__ __forceinline__ unsigned long long pack2(float a) {
  unsigned long long r;
  const unsigned int u = __float_as_uint(a);
  asm("mov.b64 %0, {%1, %1};" : "=l"(r) : "r"(u));
  return r;
}
__device__ __forceinline__ void ffma2(unsigned long long& d,
                                      unsigned long long a,
                                      unsigned long long b) {
  asm("fma.rn.f32x2 %0, %1, %2, %0;" : "+l"(d) : "l"(a), "l"(b));
}

__global__ void __launch_bounds__(256, 2) conv_kernel(const float* __restrict__ wgt,
                                                      const float* __restrict__ bias,
                                                      float* __restrict__ out) {
  const int ocg  = blockIdx.x;          // 0..3  -> oc0 = 128*ocg
  const int tile = blockIdx.y;          // 0..63 -> 8x8 grid of 8x8-pixel tiles
  const int n    = blockIdx.z;          // image
  const int trow = tile >> 3, tcol = tile & 7;
  const int t  = threadIdx.x;
  const int og = t & 15;                // oc sub-group: oc_local = og*8 .. +7
  const int sg = t >> 4;                // spatial sub-group
  const int sr = sg >> 2, sc = sg & 3;  // thread covers out rows {2sr,2sr+1}, cols {2sc,2sc+1}
  const int oc0 = ocg * 128;

  // 34.3KB raw smem: main loop uses the first 2984 floats, epilogue all of it.
  __shared__ __align__(16) float smem[64 * 134];
  float* wS = smem;            // [2][9*128]   tap-major weights (double buffered)
  float* iS = smem + 2304;     // [2][17*20]   input patch, row stride 20

  // ---- precomputed load offsets (ic-invariant) ----
  int wg_ofs[5], ws_ofs[5];
#pragma unroll
  for (int k = 0; k < 5; ++k) {
    const int idx = t + k * 256;               // 0..1279, valid < 1152
    const int oc = idx / 9, tap = idx - oc * 9;
    wg_ofs[k] = (oc0 + oc) * 2304 + tap;       // + ic*9 at use
    ws_ofs[k] = tap * 128 + oc;
  }
  const int i_row0 = t / 17, i_col0 = t - i_row0 * 17;
  const int idx1 = t + 256;                    // second patch element, valid < 289
  const int i_row1 = idx1 / 17, i_col1 = idx1 - i_row1 * 17;

  const float* gb_base = g_blur + (size_t)n * (C_IN * HB * WB)
                         + trow * 16 * WB + tcol * 16;

  float wr[5], ir0 = 0.f, ir1 = 0.f;

  // ---- prologue: load ic=0 into buffer 0 ----
#pragma unroll
  for (int k = 0; k < 5; ++k)
    if (t + k * 256 < 1152) wr[k] = wgt[wg_ofs[k]];
  ir0 = gb_base[i_row0 * WB + i_col0];
  if (idx1 < 289) ir1 = gb_base[i_row1 * WB + i_col1];
#pragma unroll
  for (int k = 0; k < 5; ++k)
    if (t + k * 256 < 1152) wS[ws_ofs[k]] = wr[k];
  iS[i_row0 * 20 + i_col0] = ir0;
  if (idx1 < 289) iS[i_row1 * 20 + i_col1] = ir1;
  __syncthreads();

  unsigned long long acc[4][4];
#pragma unroll
  for (int s = 0; s < 4; ++s)
#pragma unroll
    for (int p = 0; p < 4; ++p) acc[s][p] = 0ull;

  for (int ic = 0; ic < C_IN; ++ic) {
    const int b = ic & 1;
    const bool more = (ic + 1 < C_IN);
    if (more) {  // global loads for ic+1 (latency hidden behind compute below)
      const float* wp = wgt + (ic + 1) * 9;
#pragma unroll
      for (int k = 0; k < 5; ++k)
        if (t + k * 256 < 1152) wr[k] = wp[wg_ofs[k]];
      const float* ip = gb_base + (size_t)(ic + 1) * (HB * WB);
      ir0 = ip[i_row0 * WB + i_col0];
      if (idx1 < 289) ir1 = ip[i_row1 * WB + i_col1];
    }
    {  // compute on buffer b: 9 taps x 16 packed FMA
      const float* wp = wS + b * 1152;
      const float* ip = iS + b * 340;
      const int r0i = 4 * sr, c0i = 4 * sc;
#pragma unroll
      for (int kh = 0; kh < 3; ++kh) {
#pragma unroll
        for (int kw = 0; kw < 3; ++kw) {
          const int tap = kh * 3 + kw;
          const float* wt = wp + tap * 128 + og * 8;
          const ulonglong2 wA = *reinterpret_cast<const ulonglong2*>(wt);
          const ulonglong2 wB = *reinterpret_cast<const ulonglong2*>(wt + 4);
          const unsigned long long I00 = pack2(ip[(r0i + kh) * 20 + c0i + kw]);
          const unsigned long long I01 = pack2(ip[(r0i + kh) * 20 + c0i + 2 + kw]);
          const unsigned long long I10 = pack2(ip[(r0i + 2 + kh) * 20 + c0i + kw]);
          const unsigned long long I11 = pack2(ip[(r0i + 2 + kh) * 20 + c0i + 2 + kw]);
          ffma2(acc[0][0], I00, wA.x); ffma2(acc[0][1], I00, wA.y);
          ffma2(acc[0][2], I00, wB.x); ffma2(acc[0][3], I00, wB.y);
          ffma2(acc[1][0], I01, wA.x); ffma2(acc[1][1], I01, wA.y);
          ffma2(acc[1][2], I01, wB.x); ffma2(acc[1][3], I01, wB.y);
          ffma2(acc[2][0], I10, wA.x); ffma2(acc[2][1], I10, wA.y);
          ffma2(acc[2][2], I10, wB.x); ffma2(acc[2][3], I10, wB.y);
          ffma2(acc[3][0], I11, wA.x); ffma2(acc[3][1], I11, wA.y);
          ffma2(acc[3][2], I11, wB.x); ffma2(acc[3][3], I11, wB.y);
        }
      }
    }
    if (more) {  // stage ic+1 into the other buffer
      float* wd = wS + (1 - b) * 1152;
      float* id = iS + (1 - b) * 340;
#pragma unroll
      for (int k = 0; k < 5; ++k)
        if (t + k * 256 < 1152) wd[ws_ofs[k]] = wr[k];
      id[i_row0 * 20 + i_col0] = ir0;
      if (idx1 < 289) id[i_row1 * 20 + i_col1] = ir1;
    }
    __syncthreads();
  }

  // ---- epilogue: transpose through smem for coalesced stores ----
  float* sO = smem;  // [64 spatial][134] (pad keeps float2 stores aligned)
#pragma unroll
  for (int s = 0; s < 4; ++s) {
    const int r = 2 * sr + (s >> 1), c = 2 * sc + (s & 1);
    const int sp = r * 8 + c;
#pragma unroll
    for (int p = 0; p < 4; ++p) {
      const float2 v = *reinterpret_cast<const float2*>(&acc[s][p]);
      *reinterpret_cast<float2*>(&sO[sp * 134 + og * 8 + 2 * p]) = v;
    }
  }
  __syncthreads();

  const int oh0 = trow * 8, ow0 = tcol * 8;
#pragma unroll
  for (int k2 = 0; k2 < 32; ++k2) {
    const int idx = k2 * 256 + t;       // 0..8191
    const int oc_l = idx >> 6;
    const int sp = idx & 63;
    const int oh = oh0 + (sp >> 3), ow = ow0 + (sp & 7);
    const int oc = oc0 + oc_l;
    out[((n * C_OUT + oc) << 12) + (oh << 6) + ow] = sO[sp * 134 + oc_l] + bias[oc];
  }
}

// ---------------------------------------------------------------------------
extern "C" void kernel_launch(void* const* d_in, const int* in_sizes, int n_in,
                              void* d_out, int out_size) {
  (void)in_sizes; (void)n_in; (void)out_size;
  const float* x    = (const float*)d_in[0];  // [16,256,128,128]
  const float* wgt  = (const float*)d_in[1];  // [512,256,3,3]
  const float* bias = (const float*)d_in[2];  // [512]
  const float* bk   = (const float*)d_in[3];  // [4,4]
  float* out = (float*)d_out;                 // [16,512,64,64]

  blur_kernel<<<dim3(N_IMG * C_IN, (HB + CHUNK - 1) / CHUNK), 256>>>(x, bk);
  conv_kernel<<<dim3(4, 64, N_IMG), 256>>>(wgt, bias, out);
}

// round 4
// speedup vs baseline: 3.8043x; 3.8043x over previous
#include <cuda_runtime.h>
#include <cuda_bf16.h>
#include <cstdint>

#define N_IMG 16
#define C_IN  256
#define H_IN  128
#define W_IN  128
#define HB    129
#define C_OUT 512

// ---- device scratch (allowed: __device__ globals) ----
__device__ __align__(256) __nv_bfloat16 g_hi[(size_t)N_IMG * HB * HB * C_IN];
__device__ __align__(256) __nv_bfloat16 g_lo[(size_t)N_IMG * HB * HB * C_IN];
__device__ __align__(256) __nv_bfloat16 g_whi[(size_t)C_OUT * 9 * C_IN];
__device__ __align__(256) __nv_bfloat16 g_wlo[(size_t)C_OUT * 9 * C_IN];

// ---------------------------------------------------------------------------
// helpers (base sm_103-safe PTX only: ldmatrix / mma.sync / cp.async)
// ---------------------------------------------------------------------------
__device__ __forceinline__ uint32_t s2u(const void* p) {
  uint32_t a;
  asm("{ .reg .u64 t; cvta.to.shared.u64 t, %1; cvt.u32.u64 %0, t; }" : "=r"(a) : "l"(p));
  return a;
}
__device__ __forceinline__ void cpa16(uint32_t d, const void* s) {
  asm volatile("cp.async.cg.shared.global [%0], [%1], 16;" :: "r"(d), "l"(s));
}
__device__ __forceinline__ void cpa_commit() {
  asm volatile("cp.async.commit_group;" ::: "memory");
}
template <int N>
__device__ __forceinline__ void cpa_wait() {
  asm volatile("cp.async.wait_group %0;" :: "n"(N) : "memory");
}
__device__ __forceinline__ void ldm4(uint32_t* r, uint32_t addr) {
  asm volatile("ldmatrix.sync.aligned.m8n8.x4.shared.b16 {%0,%1,%2,%3}, [%4];"
               : "=r"(r[0]), "=r"(r[1]), "=r"(r[2]), "=r"(r[3]) : "r"(addr));
}
__device__ __forceinline__ void mma16816(float* d, const uint32_t* a,
                                         uint32_t b0, uint32_t b1) {
  asm volatile(
      "mma.sync.aligned.m16n8k16.row.col.f32.bf16.bf16.f32 "
      "{%0,%1,%2,%3}, {%4,%5,%6,%7}, {%8,%9}, {%0,%1,%2,%3};"
      : "+f"(d[0]), "+f"(d[1]), "+f"(d[2]), "+f"(d[3])
      : "r"(a[0]), "r"(a[1]), "r"(a[2]), "r"(a[3]), "r"(b0), "r"(b1));
}

// ---------------------------------------------------------------------------
// Kernel 1: weight split.  w[oc][ic][kh][kw] fp32 -> w_hi/w_lo[oc][tap][ic] bf16
// ---------------------------------------------------------------------------
__global__ void __launch_bounds__(256) wsplit_kernel(const float* __restrict__ w) {
  const int idx = blockIdx.x * 256 + threadIdx.x;  // < 512*9*256 exactly
  const int oc = idx / (9 * C_IN);
  const int r = idx - oc * 9 * C_IN;
  const int tap = r >> 8;
  const int ic = r & 255;
  const float val = w[(oc * C_IN + ic) * 9 + tap];
  const __nv_bfloat16 hi = __float2bfloat16(val);
  g_whi[idx] = hi;
  g_wlo[idx] = __float2bfloat16(val - __bfloat162float(hi));
}

// ---------------------------------------------------------------------------
// Kernel 2: separable 4x4 blur -> NHWC bf16 hi/lo, prescaled by 1/48.
// CTA = (icg of 32 ic, output row h, image n). 256 thr = 32 ic x 8 w-slices.
// ---------------------------------------------------------------------------
__global__ void __launch_bounds__(256) blur_kernel(const float* __restrict__ x,
                                                   const float* __restrict__ bk) {
  const int icg = blockIdx.x;   // 0..7
  const int h   = blockIdx.y;   // 0..128
  const int n   = blockIdx.z;   // 0..15
  const int t = threadIdx.x;
  const int ic_l = t & 31;
  const int ws = t >> 5;        // 0..7

  float vco[4], wco[4];
#pragma unroll
  for (int i = 0; i < 4; ++i) vco[i] = bk[i * 4] + bk[i * 4 + 1] + bk[i * 4 + 2] + bk[i * 4 + 3];
#pragma unroll
  for (int j = 0; j < 4; ++j) wco[j] = bk[j] + bk[4 + j] + bk[8 + j] + bk[12 + j];

  __shared__ __nv_bfloat16 sHi[HB][32];
  __shared__ __nv_bfloat16 sLo[HB][32];

  const float* xp = x + (size_t)(n * C_IN + icg * 32 + ic_l) * (H_IN * W_IN);

  // vertical pass into 24-wide register strip covering cols [ws*16-4, ws*16+20)
  float4 v[6];
#pragma unroll
  for (int m = 0; m < 6; ++m) v[m] = make_float4(0.f, 0.f, 0.f, 0.f);
#pragma unroll
  for (int i = 0; i < 4; ++i) {
    const int r = h - 2 + i;
    if (r < 0 || r >= H_IN) continue;
    const float4* rp = reinterpret_cast<const float4*>(xp + r * W_IN);
    const float c = vco[i];
#pragma unroll
    for (int m = 0; m < 6; ++m) {
      const int c4 = ws * 4 - 1 + m;
      if (c4 >= 0 && c4 < 32) {
        const float4 d = rp[c4];
        v[m].x += c * d.x; v[m].y += c * d.y; v[m].z += c * d.z; v[m].w += c * d.w;
      }
    }
  }
  float vv[24];
#pragma unroll
  for (int m = 0; m < 6; ++m) {
    vv[4 * m] = v[m].x; vv[4 * m + 1] = v[m].y; vv[4 * m + 2] = v[m].z; vv[4 * m + 3] = v[m].w;
  }
  // horizontal pass; slice 7 also produces w=128
#pragma unroll
  for (int k = 0; k < 17; ++k) {
    if (k == 16 && ws != 7) break;
    float s = wco[0] * vv[k + 2] + wco[1] * vv[k + 3] + wco[2] * vv[k + 4] + wco[3] * vv[k + 5];
    s *= 0.020833333333333332f;  // fold EqualizedLR 1/sqrt(2304)
    const __nv_bfloat16 hi = __float2bfloat16(s);
    const int w = ws * 16 + k;
    sHi[w][ic_l] = hi;
    sLo[w][ic_l] = __float2bfloat16(s - __bfloat162float(hi));
  }
  __syncthreads();

  const size_t base = ((size_t)(n * HB + h) * HB) * C_IN + icg * 32;
  for (int e = t; e < HB * 32; e += 256) {
    const int w = e >> 5, il = e & 31;
    const size_t go = base + (size_t)w * C_IN + il;
    g_hi[go] = sHi[w][il];
    g_lo[go] = sLo[w][il];
  }
}

// ---------------------------------------------------------------------------
// Kernel 3: mma.sync bf16-split implicit GEMM.
// CTA: 128 oc (M) x 128 spatial (N = 2 output rows x 64 cols), 8 warps 2x4,
// warp tile 64x32. K: 9 taps x 4 ic-chunks(64); per step 3 split-chains.
// Stages double-buffered via cp.async: 4 tiles x 16KB x 2 = 128KB smem.
// ---------------------------------------------------------------------------
#define ST_A_HI 0
#define ST_A_LO 16384
#define ST_B_HI 32768
#define ST_B_LO 49152
#define STAGE   65536
#define SMEM_BYTES (2 * STAGE)

extern __shared__ char csm[];

__global__ void __launch_bounds__(256, 1) conv_mma_kernel(const float* __restrict__ bias,
                                                          float* __restrict__ out) {
  const int t = threadIdx.x;
  const int l = t & 31, w = t >> 5;
  const int wm = w >> 2, wn = w & 3;
  const int ocg = blockIdx.x;              // 0..3
  const int by = blockIdx.y;               // 0..511
  const int n = by >> 5, rp = by & 31;
  const int oh0 = rp * 2;
  const int oc0 = ocg * 128;

  const uint32_t sb = s2u(csm);

  // staging coords (16 cp.async of 16B per thread per stage)
  int s_row[4], s_c[4];
#pragma unroll
  for (int k = 0; k < 4; ++k) {
    const int idx = t + k * 256;           // 0..1023
    s_row[k] = idx >> 3;
    s_c[k] = idx & 7;
  }

  // ldmatrix lane-invariant parts
  const int rl = l & 15;
  const int chh = l >> 4;
  const uint32_t xorm = (uint32_t)((rl & 7) << 4);
  const uint32_t aRow = (uint32_t)((wm * 64 + rl) * 128);
  const uint32_t bRow = (uint32_t)((wn * 32 + rl) * 128);

  float acc[4][4][4];
#pragma unroll
  for (int i = 0; i < 4; ++i)
#pragma unroll
    for (int j = 0; j < 4; ++j)
#pragma unroll
      for (int p = 0; p < 4; ++p) acc[i][j][p] = 0.f;

  auto stage = [&](int s) {
    const int chunk = s / 9;
    const int tap = s - chunk * 9;
    const int ic0 = chunk * 64;
    const int kh = tap / 3, kw = tap - kh * 3;
    const uint32_t stb = sb + (uint32_t)(s & 1) * STAGE;
#pragma unroll
    for (int k = 0; k < 4; ++k) {
      const int row = s_row[k], c = s_c[k];
      const uint32_t sts = (uint32_t)(row * 128 + ((c * 16) ^ ((row & 7) << 4)));
      const size_t ea = ((size_t)(oc0 + row) * 9 + tap) * C_IN + ic0 + c * 8;
      cpa16(stb + ST_A_HI + sts, g_whi + ea);
      cpa16(stb + ST_A_LO + sts, g_wlo + ea);
      const int hh = 2 * (oh0 + (row >> 6)) + kh;
      const int ww = 2 * (row & 63) + kw;
      const size_t eb = ((size_t)(n * HB + hh) * HB + ww) * C_IN + ic0 + c * 8;
      cpa16(stb + ST_B_HI + sts, g_hi + eb);
      cpa16(stb + ST_B_LO + sts, g_lo + eb);
    }
    cpa_commit();
  };

  stage(0);

  for (int step = 0; step < 36; ++step) {
    if (step + 1 < 36) {
      stage(step + 1);
      cpa_wait<1>();
    } else {
      cpa_wait<0>();
    }
    __syncthreads();

    const uint32_t st = sb + (uint32_t)(step & 1) * STAGE;
#pragma unroll
    for (int split = 0; split < 3; ++split) {
      const uint32_t aT = st + (split == 1 ? ST_A_LO : ST_A_HI);
      const uint32_t bT = st + (split == 2 ? ST_B_LO : ST_B_HI);
#pragma unroll
      for (int kk = 0; kk < 4; ++kk) {
        const uint32_t col = (uint32_t)((kk * 32 + chh * 16)) ^ xorm;
        uint32_t a[4][4];
#pragma unroll
        for (int i = 0; i < 4; ++i) ldm4(a[i], aT + aRow + i * 2048 + col);
        uint32_t b0[4], b1[4];
        ldm4(b0, bT + bRow + col);           // n 0..15 of warp tile
        ldm4(b1, bT + bRow + 2048 + col);    // n 16..31
#pragma unroll
        for (int i = 0; i < 4; ++i) {
          mma16816(acc[i][0], a[i], b0[0], b0[2]);
          mma16816(acc[i][1], a[i], b0[1], b0[3]);
          mma16816(acc[i][2], a[i], b1[0], b1[2]);
          mma16816(acc[i][3], a[i], b1[1], b1[3]);
        }
      }
    }
    __syncthreads();
  }

  // ---- epilogue: bias + direct float2 stores (frag cols = consecutive ow) ----
  const int q = l >> 2, r2 = l & 3;
#pragma unroll
  for (int i = 0; i < 4; ++i) {
    const int ocA = oc0 + wm * 64 + i * 16 + q;
    const float bvA = bias[ocA];
    const float bvB = bias[ocA + 8];
    float* baseA = out + ((size_t)(n * C_OUT + ocA)) * 4096;
    float* baseB = baseA + (size_t)8 * 4096;
#pragma unroll
    for (int nn = 0; nn < 4; ++nn) {
      const int sp = wn * 32 + nn * 8 + 2 * r2;
      const int off = (oh0 + (sp >> 6)) * 64 + (sp & 63);
      float2 v0 = make_float2(acc[i][nn][0] + bvA, acc[i][nn][1] + bvA);
      float2 v1 = make_float2(acc[i][nn][2] + bvB, acc[i][nn][3] + bvB);
      *reinterpret_cast<float2*>(baseA + off) = v0;
      *reinterpret_cast<float2*>(baseB + off) = v1;
    }
  }
}

// ---------------------------------------------------------------------------
extern "C" void kernel_launch(void* const* d_in, const int* in_sizes, int n_in,
                              void* d_out, int out_size) {
  (void)in_sizes; (void)n_in; (void)out_size;
  const float* x    = (const float*)d_in[0];  // [16,256,128,128]
  const float* wgt  = (const float*)d_in[1];  // [512,256,3,3]
  const float* bias = (const float*)d_in[2];  // [512]
  const float* bk   = (const float*)d_in[3];  // [4,4]
  float* out = (float*)d_out;                 // [16,512,64,64]

  cudaFuncSetAttribute(conv_mma_kernel, cudaFuncAttributeMaxDynamicSharedMemorySize,
                       SMEM_BYTES);
  wsplit_kernel<<<(C_OUT * 9 * C_IN) / 256, 256>>>(wgt);
  blur_kernel<<<dim3(8, HB, N_IMG), 256>>>(x, bk);
  conv_mma_kernel<<<dim3(4, 512), 256, SMEM_BYTES>>>(bias, out);
}

// round 5
// speedup vs baseline: 3.8253x; 1.0055x over previous
#include <cuda_runtime.h>
#include <cuda_bf16.h>
#include <cstdint>

#define N_IMG 16
#define C_IN  256
#define H_IN  128
#define W_IN  128
#define HB    129
#define C_OUT 512

// ---- device scratch (allowed: __device__ globals) ----
__device__ __align__(256) __nv_bfloat16 g_hi[(size_t)N_IMG * HB * HB * C_IN];
__device__ __align__(256) __nv_bfloat16 g_lo[(size_t)N_IMG * HB * HB * C_IN];
__device__ __align__(256) __nv_bfloat16 g_whi[(size_t)C_OUT * 9 * C_IN];
__device__ __align__(256) __nv_bfloat16 g_wlo[(size_t)C_OUT * 9 * C_IN];

// ---------------------------------------------------------------------------
// helpers (base sm_103-safe PTX only: ldmatrix / mma.sync / cp.async)
// ---------------------------------------------------------------------------
__device__ __forceinline__ uint32_t s2u(const void* p) {
  uint32_t a;
  asm("{ .reg .u64 t; cvta.to.shared.u64 t, %1; cvt.u32.u64 %0, t; }" : "=r"(a) : "l"(p));
  return a;
}
__device__ __forceinline__ void cpa16(uint32_t d, const void* s) {
  asm volatile("cp.async.cg.shared.global [%0], [%1], 16;" :: "r"(d), "l"(s));
}
__device__ __forceinline__ void cpa_commit() {
  asm volatile("cp.async.commit_group;" ::: "memory");
}
template <int N>
__device__ __forceinline__ void cpa_wait() {
  asm volatile("cp.async.wait_group %0;" :: "n"(N) : "memory");
}
__device__ __forceinline__ void ldm4(uint32_t* r, uint32_t addr) {
  asm volatile("ldmatrix.sync.aligned.m8n8.x4.shared.b16 {%0,%1,%2,%3}, [%4];"
               : "=r"(r[0]), "=r"(r[1]), "=r"(r[2]), "=r"(r[3]) : "r"(addr));
}
__device__ __forceinline__ void mma16816(float* d, const uint32_t* a,
                                         uint32_t b0, uint32_t b1) {
  asm volatile(
      "mma.sync.aligned.m16n8k16.row.col.f32.bf16.bf16.f32 "
      "{%0,%1,%2,%3}, {%4,%5,%6,%7}, {%8,%9}, {%0,%1,%2,%3};"
      : "+f"(d[0]), "+f"(d[1]), "+f"(d[2]), "+f"(d[3])
      : "r"(a[0]), "r"(a[1]), "r"(a[2]), "r"(a[3]), "r"(b0), "r"(b1));
}
__device__ __forceinline__ uint32_t swz(uint32_t x) { return x ^ ((x >> 3) & 0x70); }

// ---------------------------------------------------------------------------
// Kernel 1: weight split.  w[oc][ic][kh][kw] fp32 -> w_hi/w_lo[oc][tap][ic] bf16
// ---------------------------------------------------------------------------
__global__ void __launch_bounds__(256) wsplit_kernel(const float* __restrict__ w) {
  const int idx = blockIdx.x * 256 + threadIdx.x;  // < 512*9*256 exactly
  const int oc = idx / (9 * C_IN);
  const int r = idx - oc * 9 * C_IN;
  const int tap = r >> 8;
  const int ic = r & 255;
  const float val = w[(oc * C_IN + ic) * 9 + tap];
  const __nv_bfloat16 hi = __float2bfloat16(val);
  g_whi[idx] = hi;
  g_wlo[idx] = __float2bfloat16(val - __bfloat162float(hi));
}

// ---------------------------------------------------------------------------
// Kernel 2: separable 4x4 blur -> NHWC bf16 hi/lo, prescaled by 1/48.
// CTA = (icg of 32 ic, output row h, image n). 256 thr = 32 ic x 8 w-slices.
// ---------------------------------------------------------------------------
__global__ void __launch_bounds__(256) blur_kernel(const float* __restrict__ x,
                                                   const float* __restrict__ bk) {
  const int icg = blockIdx.x;   // 0..7
  const int h   = blockIdx.y;   // 0..128
  const int n   = blockIdx.z;   // 0..15
  const int t = threadIdx.x;
  const int ic_l = t & 31;
  const int ws = t >> 5;        // 0..7

  float vco[4], wco[4];
#pragma unroll
  for (int i = 0; i < 4; ++i) vco[i] = bk[i * 4] + bk[i * 4 + 1] + bk[i * 4 + 2] + bk[i * 4 + 3];
#pragma unroll
  for (int j = 0; j < 4; ++j) wco[j] = bk[j] + bk[4 + j] + bk[8 + j] + bk[12 + j];

  __shared__ __nv_bfloat16 sHi[HB][32];
  __shared__ __nv_bfloat16 sLo[HB][32];

  const float* xp = x + (size_t)(n * C_IN + icg * 32 + ic_l) * (H_IN * W_IN);

  float4 v[6];
#pragma unroll
  for (int m = 0; m < 6; ++m) v[m] = make_float4(0.f, 0.f, 0.f, 0.f);
#pragma unroll
  for (int i = 0; i < 4; ++i) {
    const int r = h - 2 + i;
    if (r < 0 || r >= H_IN) continue;
    const float4* rp = reinterpret_cast<const float4*>(xp + r * W_IN);
    const float c = vco[i];
#pragma unroll
    for (int m = 0; m < 6; ++m) {
      const int c4 = ws * 4 - 1 + m;
      if (c4 >= 0 && c4 < 32) {
        const float4 d = rp[c4];
        v[m].x += c * d.x; v[m].y += c * d.y; v[m].z += c * d.z; v[m].w += c * d.w;
      }
    }
  }
  float vv[24];
#pragma unroll
  for (int m = 0; m < 6; ++m) {
    vv[4 * m] = v[m].x; vv[4 * m + 1] = v[m].y; vv[4 * m + 2] = v[m].z; vv[4 * m + 3] = v[m].w;
  }
#pragma unroll
  for (int k = 0; k < 17; ++k) {
    if (k == 16 && ws != 7) break;
    float s = wco[0] * vv[k + 2] + wco[1] * vv[k + 3] + wco[2] * vv[k + 4] + wco[3] * vv[k + 5];
    s *= 0.020833333333333332f;  // fold EqualizedLR 1/sqrt(2304)
    const __nv_bfloat16 hi = __float2bfloat16(s);
    const int w = ws * 16 + k;
    sHi[w][ic_l] = hi;
    sLo[w][ic_l] = __float2bfloat16(s - __bfloat162float(hi));
  }
  __syncthreads();

  const size_t base = ((size_t)(n * HB + h) * HB) * C_IN + icg * 32;
  for (int e = t; e < HB * 32; e += 256) {
    const int w = e >> 5, il = e & 31;
    const size_t go = base + (size_t)w * C_IN + il;
    g_hi[go] = sHi[w][il];
    g_lo[go] = sLo[w][il];
  }
}

// ---------------------------------------------------------------------------
// Kernel 3: mma.sync bf16-split implicit GEMM with tap-shared B tiles.
// CTA: 128 oc x 128 spatial (2 out rows x 64 cols). 8 warps (2x4), warp 64x32.
// Stage = (ic-chunk of 32, kh): raw NHWC input rows {2h0+kh, 2h0+kh+2} x 129
// cols (hi+lo) + weights for the 3 kw taps. 24 stages, double-buffered.
// ldmatrix reads strided per-tap views straight from the raw tile.
// ---------------------------------------------------------------------------
#define ST_A_HI 0
#define ST_A_LO 24576
#define ST_B_HI 49152
#define ST_B_LO 65664
#define STAGE   82176
#define SMEM_BYTES (2 * STAGE)   // 164352

extern __shared__ char csm[];

__global__ void __launch_bounds__(256, 1) conv_mma_kernel(const float* __restrict__ bias,
                                                          float* __restrict__ out) {
  const int t = threadIdx.x;
  const int l = t & 31, w = t >> 5;
  const int wm = w >> 2, wn = w & 3;
  const int ocg = blockIdx.x;              // 0..3
  const int by = blockIdx.y;               // 0..511
  const int n = by >> 5, rp = by & 31;
  const int oh0 = rp * 2;
  const int oc0 = ocg * 128;
  const uint32_t sb = s2u(csm);

  // ---- staging precomputes ----
  // A: 1536 16B-chunks per (hi|lo): idx -> c(0..3), kw(0..2), oc(0..127)
  uint32_t a_sw[6], a_g[6];
#pragma unroll
  for (int k = 0; k < 6; ++k) {
    const int idx = t + k * 256;
    const int c = idx & 3, rowi = idx >> 2;
    const int kw = rowi >> 7, oc = rowi & 127;
    a_sw[k] = swz((uint32_t)(kw * 8192 + oc * 64 + c * 16));
    a_g[k] = (uint32_t)(((oc0 + oc) * 9 + kw) * C_IN + c * 8);  // + kh*768 + ic0
  }
  // B: 1032 chunks per (hi|lo): idx -> c, pixel pp(0..257) = rsel*129 + colw
  uint32_t b_sw[5], b_g[5];
#pragma unroll
  for (int k = 0; k < 5; ++k) {
    const int idx = t + k * 256;
    const int c = idx & 3, pp = idx >> 2;
    const int rsel = (pp >= 129) ? 1 : 0;
    const int colw = pp - rsel * 129;
    b_sw[k] = swz((uint32_t)(pp * 64 + c * 16));
    b_g[k] = (uint32_t)(((n * HB + 2 * oh0 + 2 * rsel) * HB + colw) * C_IN + c * 8);
  }

  // ---- compute-side precomputes ----
  const int rl = l & 15, chh = l >> 4;
  uint32_t aOff[4], aMask[4];
#pragma unroll
  for (int i = 0; i < 4; ++i) {
    const int m = wm * 64 + i * 16 + rl;
    aOff[i] = (uint32_t)(m * 64 + chh * 16);
    aMask[i] = (uint32_t)((m & 14) << 3);
  }
  const int n0 = wn * 32 + rl;
  const int pb0 = (n0 >> 6) * 129 + 2 * (n0 & 63);
  const int n1 = n0 + 16;
  const int pb1 = (n1 >> 6) * 129 + 2 * (n1 & 63);

  float acc[4][4][4];
#pragma unroll
  for (int i = 0; i < 4; ++i)
#pragma unroll
    for (int j = 0; j < 4; ++j)
#pragma unroll
      for (int p = 0; p < 4; ++p) acc[i][j][p] = 0.f;

  auto stage = [&](int s) {
    const int chunk = s / 3, kh = s - chunk * 3;
    const int ic0 = chunk * 32;
    const uint32_t stb = sb + (uint32_t)(s & 1) * STAGE;
    const uint32_t aadd = (uint32_t)(kh * 3 * C_IN + ic0);
    const uint32_t badd = (uint32_t)(kh * HB * C_IN + ic0);
#pragma unroll
    for (int k = 0; k < 6; ++k) {
      cpa16(stb + ST_A_HI + a_sw[k], g_whi + a_g[k] + aadd);
      cpa16(stb + ST_A_LO + a_sw[k], g_wlo + a_g[k] + aadd);
    }
#pragma unroll
    for (int k = 0; k < 5; ++k) {
      if (k < 4 || t < 8) {
        cpa16(stb + ST_B_HI + b_sw[k], g_hi + b_g[k] + badd);
        cpa16(stb + ST_B_LO + b_sw[k], g_lo + b_g[k] + badd);
      }
    }
    cpa_commit();
  };

  stage(0);

  for (int s = 0; s < 24; ++s) {
    if (s + 1 < 24) {
      stage(s + 1);
      cpa_wait<1>();
    } else {
      cpa_wait<0>();
    }
    __syncthreads();

    const uint32_t stb = sb + (uint32_t)(s & 1) * STAGE;
#pragma unroll
    for (int kw = 0; kw < 3; ++kw) {
      const int pix0 = pb0 + kw, pix1 = pb1 + kw;
      const uint32_t bB0 = (uint32_t)(pix0 * 64 + chh * 16);
      const uint32_t bM0 = (uint32_t)((pix0 & 14) << 3);
      const uint32_t bB1 = (uint32_t)(pix1 * 64 + chh * 16);
      const uint32_t bM1 = (uint32_t)((pix1 & 14) << 3);
      const uint32_t kwq = (uint32_t)(kw * 8192);
#pragma unroll
      for (int kk = 0; kk < 2; ++kk) {
        const uint32_t kq = (uint32_t)(kk * 32);
        uint32_t ah[4][4], al[4][4];
#pragma unroll
        for (int i = 0; i < 4; ++i) {
          const uint32_t loc = (aOff[i] + kwq + kq) ^ aMask[i];
          ldm4(ah[i], stb + ST_A_HI + loc);
          ldm4(al[i], stb + ST_A_LO + loc);
        }
        uint32_t b0h[4], b1h[4], b0l[4], b1l[4];
        const uint32_t l0 = (bB0 + kq) ^ bM0;
        const uint32_t l1 = (bB1 + kq) ^ bM1;
        ldm4(b0h, stb + ST_B_HI + l0);
        ldm4(b1h, stb + ST_B_HI + l1);
        ldm4(b0l, stb + ST_B_LO + l0);
        ldm4(b1l, stb + ST_B_LO + l1);
#pragma unroll
        for (int i = 0; i < 4; ++i) {
          mma16816(acc[i][0], ah[i], b0h[0], b0h[2]);
          mma16816(acc[i][1], ah[i], b0h[1], b0h[3]);
          mma16816(acc[i][2], ah[i], b1h[0], b1h[2]);
          mma16816(acc[i][3], ah[i], b1h[1], b1h[3]);
          mma16816(acc[i][0], al[i], b0h[0], b0h[2]);
          mma16816(acc[i][1], al[i], b0h[1], b0h[3]);
          mma16816(acc[i][2], al[i], b1h[0], b1h[2]);
          mma16816(acc[i][3], al[i], b1h[1], b1h[3]);
          mma16816(acc[i][0], ah[i], b0l[0], b0l[2]);
          mma16816(acc[i][1], ah[i], b0l[1], b0l[3]);
          mma16816(acc[i][2], ah[i], b1l[0], b1l[2]);
          mma16816(acc[i][3], ah[i], b1l[1], b1l[3]);
        }
      }
    }
    __syncthreads();
  }

  // ---- epilogue: bias + direct float2 stores (frag cols = consecutive ow) ----
  const int q = l >> 2, r2 = l & 3;
#pragma unroll
  for (int i = 0; i < 4; ++i) {
    const int ocA = oc0 + wm * 64 + i * 16 + q;
    const float bvA = bias[ocA];
    const float bvB = bias[ocA + 8];
    float* baseA = out + ((size_t)(n * C_OUT + ocA)) * 4096;
    float* baseB = baseA + (size_t)8 * 4096;
#pragma unroll
    for (int nn = 0; nn < 4; ++nn) {
      const int sp = wn * 32 + nn * 8 + 2 * r2;
      const int off = (oh0 + (sp >> 6)) * 64 + (sp & 63);
      float2 v0 = make_float2(acc[i][nn][0] + bvA, acc[i][nn][1] + bvA);
      float2 v1 = make_float2(acc[i][nn][2] + bvB, acc[i][nn][3] + bvB);
      *reinterpret_cast<float2*>(baseA + off) = v0;
      *reinterpret_cast<float2*>(baseB + off) = v1;
    }
  }
}

// ---------------------------------------------------------------------------
extern "C" void kernel_launch(void* const* d_in, const int* in_sizes, int n_in,
                              void* d_out, int out_size) {
  (void)in_sizes; (void)n_in; (void)out_size;
  const float* x    = (const float*)d_in[0];  // [16,256,128,128]
  const float* wgt  = (const float*)d_in[1];  // [512,256,3,3]
  const float* bias = (const float*)d_in[2];  // [512]
  const float* bk   = (const float*)d_in[3];  // [4,4]
  float* out = (float*)d_out;                 // [16,512,64,64]

  cudaFuncSetAttribute(conv_mma_kernel, cudaFuncAttributeMaxDynamicSharedMemorySize,
                       SMEM_BYTES);
  wsplit_kernel<<<(C_OUT * 9 * C_IN) / 256, 256>>>(wgt);
  blur_kernel<<<dim3(8, HB, N_IMG), 256>>>(x, bk);
  conv_mma_kernel<<<dim3(4, 512), 256, SMEM_BYTES>>>(bias, out);
}

// round 6
// speedup vs baseline: 5.0635x; 1.3237x over previous
#include <cuda_runtime.h>
#include <cuda_fp16.h>
#include <cstdint>

#define N_IMG 16
#define C_IN  256
#define H_IN  128
#define W_IN  128
#define HB    129
#define C_OUT 512

// ---- device scratch (allowed: __device__ globals) ----
__device__ __align__(256) __half g_act[(size_t)N_IMG * HB * HB * C_IN];   // fp16 activations (unscaled)
__device__ __align__(256) __half g_whi[(size_t)C_OUT * 9 * C_IN];
__device__ __align__(256) __half g_wlo[(size_t)C_OUT * 9 * C_IN];

// ---------------------------------------------------------------------------
// helpers (base sm_103-safe PTX only: ldmatrix / mma.sync / cp.async)
// ---------------------------------------------------------------------------
__device__ __forceinline__ uint32_t s2u(const void* p) {
  uint32_t a;
  asm("{ .reg .u64 t; cvta.to.shared.u64 t, %1; cvt.u32.u64 %0, t; }" : "=r"(a) : "l"(p));
  return a;
}
__device__ __forceinline__ void cpa16(uint32_t d, const void* s) {
  asm volatile("cp.async.cg.shared.global [%0], [%1], 16;" :: "r"(d), "l"(s));
}
__device__ __forceinline__ void cpa_commit() {
  asm volatile("cp.async.commit_group;" ::: "memory");
}
template <int N>
__device__ __forceinline__ void cpa_wait() {
  asm volatile("cp.async.wait_group %0;" :: "n"(N) : "memory");
}
__device__ __forceinline__ void ldm4(uint32_t* r, uint32_t addr) {
  asm volatile("ldmatrix.sync.aligned.m8n8.x4.shared.b16 {%0,%1,%2,%3}, [%4];"
               : "=r"(r[0]), "=r"(r[1]), "=r"(r[2]), "=r"(r[3]) : "r"(addr));
}
__device__ __forceinline__ void mma16816(float* d, const uint32_t* a,
                                         uint32_t b0, uint32_t b1) {
  asm volatile(
      "mma.sync.aligned.m16n8k16.row.col.f32.f16.f16.f32 "
      "{%0,%1,%2,%3}, {%4,%5,%6,%7}, {%8,%9}, {%0,%1,%2,%3};"
      : "+f"(d[0]), "+f"(d[1]), "+f"(d[2]), "+f"(d[3])
      : "r"(a[0]), "r"(a[1]), "r"(a[2]), "r"(a[3]), "r"(b0), "r"(b1));
}
__device__ __forceinline__ uint32_t swz(uint32_t x) { return x ^ ((x >> 3) & 0x70); }

// ---------------------------------------------------------------------------
// Kernel 1: weight split.  w[oc][ic][kh][kw] fp32 -> w_hi/w_lo[oc][tap][ic] fp16
// ---------------------------------------------------------------------------
__global__ void __launch_bounds__(256) wsplit_kernel(const float* __restrict__ w) {
  const int idx = blockIdx.x * 256 + threadIdx.x;  // < 512*9*256 exactly
  const int oc = idx / (9 * C_IN);
  const int r = idx - oc * 9 * C_IN;
  const int tap = r >> 8;
  const int ic = r & 255;
  const float val = w[(oc * C_IN + ic) * 9 + tap];
  const __half hi = __float2half(val);
  g_whi[idx] = hi;
  g_wlo[idx] = __float2half(val - __half2float(hi));
}

// ---------------------------------------------------------------------------
// Kernel 2: separable 4x4 blur -> NHWC fp16 (single copy, unscaled).
// CTA = (icg of 32 ic, output row h, image n). 256 thr = 32 ic x 8 w-slices.
// ---------------------------------------------------------------------------
__global__ void __launch_bounds__(256) blur_kernel(const float* __restrict__ x,
                                                   const float* __restrict__ bk) {
  const int icg = blockIdx.x;   // 0..7
  const int h   = blockIdx.y;   // 0..128
  const int n   = blockIdx.z;   // 0..15
  const int t = threadIdx.x;
  const int ic_l = t & 31;
  const int ws = t >> 5;        // 0..7

  float vco[4], wco[4];
#pragma unroll
  for (int i = 0; i < 4; ++i) vco[i] = bk[i * 4] + bk[i * 4 + 1] + bk[i * 4 + 2] + bk[i * 4 + 3];
#pragma unroll
  for (int j = 0; j < 4; ++j) wco[j] = bk[j] + bk[4 + j] + bk[8 + j] + bk[12 + j];

  __shared__ __half sA[HB][32];

  const float* xp = x + (size_t)(n * C_IN + icg * 32 + ic_l) * (H_IN * W_IN);

  float4 v[6];
#pragma unroll
  for (int m = 0; m < 6; ++m) v[m] = make_float4(0.f, 0.f, 0.f, 0.f);
#pragma unroll
  for (int i = 0; i < 4; ++i) {
    const int r = h - 2 + i;
    if (r < 0 || r >= H_IN) continue;
    const float4* rp = reinterpret_cast<const float4*>(xp + r * W_IN);
    const float c = vco[i];
#pragma unroll
    for (int m = 0; m < 6; ++m) {
      const int c4 = ws * 4 - 1 + m;
      if (c4 >= 0 && c4 < 32) {
        const float4 d = rp[c4];
        v[m].x += c * d.x; v[m].y += c * d.y; v[m].z += c * d.z; v[m].w += c * d.w;
      }
    }
  }
  float vv[24];
#pragma unroll
  for (int m = 0; m < 6; ++m) {
    vv[4 * m] = v[m].x; vv[4 * m + 1] = v[m].y; vv[4 * m + 2] = v[m].z; vv[4 * m + 3] = v[m].w;
  }
#pragma unroll
  for (int k = 0; k < 17; ++k) {
    if (k == 16 && ws != 7) break;
    float s = wco[0] * vv[k + 2] + wco[1] * vv[k + 3] + wco[2] * vv[k + 4] + wco[3] * vv[k + 5];
    sA[ws * 16 + k][ic_l] = __float2half(s);
  }
  __syncthreads();

  const size_t base = ((size_t)(n * HB + h) * HB) * C_IN + icg * 32;
  for (int e = t; e < HB * 32; e += 256) {
    const int w = e >> 5, il = e & 31;
    g_act[base + (size_t)w * C_IN + il] = sA[w][il];
  }
}

// ---------------------------------------------------------------------------
// Kernel 3: mma.sync fp16 2-chain implicit GEMM with tap-shared B tiles.
// D = (Ahi + Alo) * B  (A = weights split exactly; B = fp16-rounded act).
// CTA: 128 oc x 128 spatial (2 out rows x 64 cols). 8 warps (2x4), warp 64x32.
// Stage = (ic-chunk of 32, kh): raw NHWC rows {2h0+kh, 2h0+kh+2} x 129 cols
// + weights for the 3 kw taps (hi+lo). 24 stages, double-buffered.
// ---------------------------------------------------------------------------
#define ST_A_HI 0
#define ST_A_LO 24576
#define ST_B    49152
#define STAGE   65664
#define SMEM_BYTES (2 * STAGE)   // 131328

extern __shared__ char csm[];

__global__ void __launch_bounds__(256, 1) conv_mma_kernel(const float* __restrict__ bias,
                                                          float* __restrict__ out) {
  const int t = threadIdx.x;
  const int l = t & 31, w = t >> 5;
  const int wm = w >> 2, wn = w & 3;
  const int ocg = blockIdx.x;              // 0..3
  const int by = blockIdx.y;               // 0..511
  const int n = by >> 5, rp = by & 31;
  const int oh0 = rp * 2;
  const int oc0 = ocg * 128;
  const uint32_t sb = s2u(csm);

  // ---- staging precomputes ----
  // A: 1536 16B-chunks per (hi|lo): idx -> c(0..3), kw(0..2), oc(0..127)
  uint32_t a_sw[6], a_g[6];
#pragma unroll
  for (int k = 0; k < 6; ++k) {
    const int idx = t + k * 256;
    const int c = idx & 3, rowi = idx >> 2;
    const int kw = rowi >> 7, oc = rowi & 127;
    a_sw[k] = swz((uint32_t)(kw * 8192 + oc * 64 + c * 16));
    a_g[k] = (uint32_t)(((oc0 + oc) * 9 + kw) * C_IN + c * 8);  // + kh*768 + ic0
  }
  // B: 1032 chunks: idx -> c, pixel pp(0..257) = rsel*129 + colw
  uint32_t b_sw[5], b_g[5];
#pragma unroll
  for (int k = 0; k < 5; ++k) {
    const int idx = t + k * 256;
    const int c = idx & 3, pp = idx >> 2;
    const int rsel = (pp >= 129) ? 1 : 0;
    const int colw = pp - rsel * 129;
    b_sw[k] = swz((uint32_t)(pp * 64 + c * 16));
    b_g[k] = (uint32_t)(((n * HB + 2 * oh0 + 2 * rsel) * HB + colw) * C_IN + c * 8);
  }

  // ---- compute-side precomputes ----
  const int rl = l & 15, chh = l >> 4;
  uint32_t aOff[4], aMask[4];
#pragma unroll
  for (int i = 0; i < 4; ++i) {
    const int m = wm * 64 + i * 16 + rl;
    aOff[i] = (uint32_t)(m * 64 + chh * 16);
    aMask[i] = (uint32_t)((m & 14) << 3);
  }
  const int n0 = wn * 32 + rl;
  const int pb0 = (n0 >> 6) * 129 + 2 * (n0 & 63);
  const int n1 = n0 + 16;
  const int pb1 = (n1 >> 6) * 129 + 2 * (n1 & 63);

  float acc[4][4][4];
#pragma unroll
  for (int i = 0; i < 4; ++i)
#pragma unroll
    for (int j = 0; j < 4; ++j)
#pragma unroll
      for (int p = 0; p < 4; ++p) acc[i][j][p] = 0.f;

  auto stage = [&](int s) {
    const int chunk = s / 3, kh = s - chunk * 3;
    const int ic0 = chunk * 32;
    const uint32_t stb = sb + (uint32_t)(s & 1) * STAGE;
    const uint32_t aadd = (uint32_t)(kh * 3 * C_IN + ic0);
    const uint32_t badd = (uint32_t)(kh * HB * C_IN + ic0);
#pragma unroll
    for (int k = 0; k < 6; ++k) {
      cpa16(stb + ST_A_HI + a_sw[k], g_whi + a_g[k] + aadd);
      cpa16(stb + ST_A_LO + a_sw[k], g_wlo + a_g[k] + aadd);
    }
#pragma unroll
    for (int k = 0; k < 5; ++k) {
      if (k < 4 || t < 8) cpa16(stb + ST_B + b_sw[k], g_act + b_g[k] + badd);
    }
    cpa_commit();
  };

  stage(0);

  for (int s = 0; s < 24; ++s) {
    if (s + 1 < 24) {
      stage(s + 1);
      cpa_wait<1>();
    } else {
      cpa_wait<0>();
    }
    __syncthreads();

    const uint32_t stb = sb + (uint32_t)(s & 1) * STAGE;
#pragma unroll
    for (int kw = 0; kw < 3; ++kw) {
      const int pix0 = pb0 + kw, pix1 = pb1 + kw;
      const uint32_t bB0 = (uint32_t)(pix0 * 64 + chh * 16);
      const uint32_t bM0 = (uint32_t)((pix0 & 14) << 3);
      const uint32_t bB1 = (uint32_t)(pix1 * 64 + chh * 16);
      const uint32_t bM1 = (uint32_t)((pix1 & 14) << 3);
      const uint32_t kwq = (uint32_t)(kw * 8192);
#pragma unroll
      for (int kk = 0; kk < 2; ++kk) {
        const uint32_t kq = (uint32_t)(kk * 32);
        uint32_t ah[4][4], al[4][4];
#pragma unroll
        for (int i = 0; i < 4; ++i) {
          const uint32_t loc = (aOff[i] + kwq + kq) ^ aMask[i];
          ldm4(ah[i], stb + ST_A_HI + loc);
          ldm4(al[i], stb + ST_A_LO + loc);
        }
        uint32_t b0h[4], b1h[4];
        ldm4(b0h, stb + ST_B + ((bB0 + kq) ^ bM0));
        ldm4(b1h, stb + ST_B + ((bB1 + kq) ^ bM1));
#pragma unroll
        for (int i = 0; i < 4; ++i) {
          mma16816(acc[i][0], ah[i], b0h[0], b0h[2]);
          mma16816(acc[i][1], ah[i], b0h[1], b0h[3]);
          mma16816(acc[i][2], ah[i], b1h[0], b1h[2]);
          mma16816(acc[i][3], ah[i], b1h[1], b1h[3]);
          mma16816(acc[i][0], al[i], b0h[0], b0h[2]);
          mma16816(acc[i][1], al[i], b0h[1], b0h[3]);
          mma16816(acc[i][2], al[i], b1h[0], b1h[2]);
          mma16816(acc[i][3], al[i], b1h[1], b1h[3]);
        }
      }
    }
    __syncthreads();
  }

  // ---- epilogue: scale (EqualizedLR 1/48) + bias + direct float2 stores ----
  const float kS = 0.020833333333333332f;
  const int q = l >> 2, r2 = l & 3;
#pragma unroll
  for (int i = 0; i < 4; ++i) {
    const int ocA = oc0 + wm * 64 + i * 16 + q;
    const float bvA = bias[ocA];
    const float bvB = bias[ocA + 8];
    float* baseA = out + ((size_t)(n * C_OUT + ocA)) * 4096;
    float* baseB = baseA + (size_t)8 * 4096;
#pragma unroll
    for (int nn = 0; nn < 4; ++nn) {
      const int sp = wn * 32 + nn * 8 + 2 * r2;
      const int off = (oh0 + (sp >> 6)) * 64 + (sp & 63);
      float2 v0 = make_float2(acc[i][nn][0] * kS + bvA, acc[i][nn][1] * kS + bvA);
      float2 v1 = make_float2(acc[i][nn][2] * kS + bvB, acc[i][nn][3] * kS + bvB);
      *reinterpret_cast<float2*>(baseA + off) = v0;
      *reinterpret_cast<float2*>(baseB + off) = v1;
    }
  }
}

// ---------------------------------------------------------------------------
extern "C" void kernel_launch(void* const* d_in, const int* in_sizes, int n_in,
                              void* d_out, int out_size) {
  (void)in_sizes; (void)n_in; (void)out_size;
  const float* x    = (const float*)d_in[0];  // [16,256,128,128]
  const float* wgt  = (const float*)d_in[1];  // [512,256,3,3]
  const float* bias = (const float*)d_in[2];  // [512]
  const float* bk   = (const float*)d_in[3];  // [4,4]
  float* out = (float*)d_out;                 // [16,512,64,64]

  cudaFuncSetAttribute(conv_mma_kernel, cudaFuncAttributeMaxDynamicSharedMemorySize,
                       SMEM_BYTES);
  wsplit_kernel<<<(C_OUT * 9 * C_IN) / 256, 256>>>(wgt);
  blur_kernel<<<dim3(8, HB, N_IMG), 256>>>(x, bk);
  conv_mma_kernel<<<dim3(4, 512), 256, SMEM_BYTES>>>(bias, out);
}

// round 7
// speedup vs baseline: 7.8541x; 1.5511x over previous
#include <cuda_runtime.h>
#include <cuda_fp16.h>
#include <cstdint>

#define N_IMG 16
#define C_IN  256
#define H_IN  128
#define W_IN  128
#define HB    129
#define C_OUT 512

// ---- device scratch (allowed: __device__ globals) ----
__device__ __align__(256) __half g_act[(size_t)N_IMG * HB * HB * C_IN];  // fp16 activations (unscaled)
__device__ __align__(256) __half g_w[(size_t)C_OUT * 9 * C_IN];          // fp16 weights [oc][tap][ic]

// ---------------------------------------------------------------------------
// helpers (base sm_103-safe PTX only: ldmatrix / mma.sync / cp.async)
// ---------------------------------------------------------------------------
__device__ __forceinline__ uint32_t s2u(const void* p) {
  uint32_t a;
  asm("{ .reg .u64 t; cvta.to.shared.u64 t, %1; cvt.u32.u64 %0, t; }" : "=r"(a) : "l"(p));
  return a;
}
__device__ __forceinline__ void cpa16(uint32_t d, const void* s) {
  asm volatile("cp.async.cg.shared.global [%0], [%1], 16;" :: "r"(d), "l"(s));
}
__device__ __forceinline__ void cpa_commit() {
  asm volatile("cp.async.commit_group;" ::: "memory");
}
template <int N>
__device__ __forceinline__ void cpa_wait() {
  asm volatile("cp.async.wait_group %0;" :: "n"(N) : "memory");
}
__device__ __forceinline__ void ldm4(uint32_t* r, uint32_t addr) {
  asm volatile("ldmatrix.sync.aligned.m8n8.x4.shared.b16 {%0,%1,%2,%3}, [%4];"
               : "=r"(r[0]), "=r"(r[1]), "=r"(r[2]), "=r"(r[3]) : "r"(addr));
}
__device__ __forceinline__ void mma16816(float* d, const uint32_t* a,
                                         uint32_t b0, uint32_t b1) {
  asm volatile(
      "mma.sync.aligned.m16n8k16.row.col.f32.f16.f16.f32 "
      "{%0,%1,%2,%3}, {%4,%5,%6,%7}, {%8,%9}, {%0,%1,%2,%3};"
      : "+f"(d[0]), "+f"(d[1]), "+f"(d[2]), "+f"(d[3])
      : "r"(a[0]), "r"(a[1]), "r"(a[2]), "r"(a[3]), "r"(b0), "r"(b1));
}
__device__ __forceinline__ uint32_t swz(uint32_t x) { return x ^ ((x >> 3) & 0x70); }

// ---------------------------------------------------------------------------
// Kernel 1: weight cast.  w[oc][ic][kh][kw] fp32 -> w[oc][tap][ic] fp16
// ---------------------------------------------------------------------------
__global__ void __launch_bounds__(256) wsplit_kernel(const float* __restrict__ w) {
  const int idx = blockIdx.x * 256 + threadIdx.x;  // < 512*9*256 exactly
  const int oc = idx / (9 * C_IN);
  const int r = idx - oc * 9 * C_IN;
  const int tap = r >> 8;
  const int ic = r & 255;
  g_w[idx] = __float2half(w[(oc * C_IN + ic) * 9 + tap]);
}

// ---------------------------------------------------------------------------
// Kernel 2: separable 4x4 blur -> NHWC fp16 (single copy, unscaled).
// CTA = (icg of 32 ic, output row h, image n). 256 thr = 32 ic x 8 w-slices.
// ---------------------------------------------------------------------------
__global__ void __launch_bounds__(256) blur_kernel(const float* __restrict__ x,
                                                   const float* __restrict__ bk) {
  const int icg = blockIdx.x;   // 0..7
  const int h   = blockIdx.y;   // 0..128
  const int n   = blockIdx.z;   // 0..15
  const int t = threadIdx.x;
  const int ic_l = t & 31;
  const int ws = t >> 5;        // 0..7

  float vco[4], wco[4];
#pragma unroll
  for (int i = 0; i < 4; ++i) vco[i] = bk[i * 4] + bk[i * 4 + 1] + bk[i * 4 + 2] + bk[i * 4 + 3];
#pragma unroll
  for (int j = 0; j < 4; ++j) wco[j] = bk[j] + bk[4 + j] + bk[8 + j] + bk[12 + j];

  __shared__ __half sA[HB][32];

  const float* xp = x + (size_t)(n * C_IN + icg * 32 + ic_l) * (H_IN * W_IN);

  float4 v[6];
#pragma unroll
  for (int m = 0; m < 6; ++m) v[m] = make_float4(0.f, 0.f, 0.f, 0.f);
#pragma unroll
  for (int i = 0; i < 4; ++i) {
    const int r = h - 2 + i;
    if (r < 0 || r >= H_IN) continue;
    const float4* rp = reinterpret_cast<const float4*>(xp + r * W_IN);
    const float c = vco[i];
#pragma unroll
    for (int m = 0; m < 6; ++m) {
      const int c4 = ws * 4 - 1 + m;
      if (c4 >= 0 && c4 < 32) {
        const float4 d = rp[c4];
        v[m].x += c * d.x; v[m].y += c * d.y; v[m].z += c * d.z; v[m].w += c * d.w;
      }
    }
  }
  float vv[24];
#pragma unroll
  for (int m = 0; m < 6; ++m) {
    vv[4 * m] = v[m].x; vv[4 * m + 1] = v[m].y; vv[4 * m + 2] = v[m].z; vv[4 * m + 3] = v[m].w;
  }
#pragma unroll
  for (int k = 0; k < 17; ++k) {
    if (k == 16 && ws != 7) break;
    float s = wco[0] * vv[k + 2] + wco[1] * vv[k + 3] + wco[2] * vv[k + 4] + wco[3] * vv[k + 5];
    sA[ws * 16 + k][ic_l] = __float2half(s);
  }
  __syncthreads();

  const size_t base = ((size_t)(n * HB + h) * HB) * C_IN + icg * 32;
  for (int e = t; e < HB * 32; e += 256) {
    const int w = e >> 5, il = e & 31;
    g_act[base + (size_t)w * C_IN + il] = sA[w][il];
  }
}

// ---------------------------------------------------------------------------
// Kernel 3: mma.sync fp16 single-chain implicit GEMM, tap-shared B tiles.
// CTA: 128 oc x 128 spatial (2 out rows x 64 cols). 8 warps (2x4), warp 64x32.
// Stage = (ic-chunk of 32, kh): raw NHWC rows {2h0+kh, 2h0+kh+2} x 129 cols
// + weights for the 3 kw taps. 24 stages, double-buffered, 2 CTAs/SM.
// ---------------------------------------------------------------------------
#define ST_A 0
#define ST_B 24576
#define STAGE 41088
#define SMEM_BYTES (2 * STAGE)   // 82176

extern __shared__ char csm[];

__global__ void __launch_bounds__(256, 2) conv_mma_kernel(const float* __restrict__ bias,
                                                          float* __restrict__ out) {
  const int t = threadIdx.x;
  const int l = t & 31, w = t >> 5;
  const int wm = w >> 2, wn = w & 3;
  const int ocg = blockIdx.x;              // 0..3
  const int by = blockIdx.y;               // 0..511
  const int n = by >> 5, rp = by & 31;
  const int oh0 = rp * 2;
  const int oc0 = ocg * 128;
  const uint32_t sb = s2u(csm);

  // ---- staging precomputes ----
  // A: 1536 16B-chunks: idx -> c(0..3), kw(0..2), oc(0..127)
  uint32_t a_sw[6], a_g[6];
#pragma unroll
  for (int k = 0; k < 6; ++k) {
    const int idx = t + k * 256;
    const int c = idx & 3, rowi = idx >> 2;
    const int kw = rowi >> 7, oc = rowi & 127;
    a_sw[k] = swz((uint32_t)(kw * 8192 + oc * 64 + c * 16));
    a_g[k] = (uint32_t)(((oc0 + oc) * 9 + kw) * C_IN + c * 8);  // + kh*768 + ic0
  }
  // B: 1032 chunks: idx -> c, pixel pp(0..257) = rsel*129 + colw
  uint32_t b_sw[5], b_g[5];
#pragma unroll
  for (int k = 0; k < 5; ++k) {
    const int idx = t + k * 256;
    const int c = idx & 3, pp = idx >> 2;
    const int rsel = (pp >= 129) ? 1 : 0;
    const int colw = pp - rsel * 129;
    b_sw[k] = swz((uint32_t)(pp * 64 + c * 16));
    b_g[k] = (uint32_t)(((n * HB + 2 * oh0 + 2 * rsel) * HB + colw) * C_IN + c * 8);
  }

  // ---- compute-side precomputes ----
  const int rl = l & 15, chh = l >> 4;
  uint32_t aOff[4], aMask[4];
#pragma unroll
  for (int i = 0; i < 4; ++i) {
    const int m = wm * 64 + i * 16 + rl;
    aOff[i] = (uint32_t)(m * 64 + chh * 16);
    aMask[i] = (uint32_t)((m & 14) << 3);
  }
  const int n0 = wn * 32 + rl;
  const int pb0 = (n0 >> 6) * 129 + 2 * (n0 & 63);
  const int n1 = n0 + 16;
  const int pb1 = (n1 >> 6) * 129 + 2 * (n1 & 63);

  float acc[4][4][4];
#pragma unroll
  for (int i = 0; i < 4; ++i)
#pragma unroll
    for (int j = 0; j < 4; ++j)
#pragma unroll
      for (int p = 0; p < 4; ++p) acc[i][j][p] = 0.f;

  auto stage = [&](int s) {
    const int chunk = s / 3, kh = s - chunk * 3;
    const int ic0 = chunk * 32;
    const uint32_t stb = sb + (uint32_t)(s & 1) * STAGE;
    const uint32_t aadd = (uint32_t)(kh * 3 * C_IN + ic0);
    const uint32_t badd = (uint32_t)(kh * HB * C_IN + ic0);
#pragma unroll
    for (int k = 0; k < 6; ++k) cpa16(stb + ST_A + a_sw[k], g_w + a_g[k] + aadd);
#pragma unroll
    for (int k = 0; k < 5; ++k) {
      if (k < 4 || t < 8) cpa16(stb + ST_B + b_sw[k], g_act + b_g[k] + badd);
    }
    cpa_commit();
  };

  stage(0);

  for (int s = 0; s < 24; ++s) {
    if (s + 1 < 24) {
      stage(s + 1);
      cpa_wait<1>();
    } else {
      cpa_wait<0>();
    }
    __syncthreads();

    const uint32_t stb = sb + (uint32_t)(s & 1) * STAGE;
#pragma unroll
    for (int kw = 0; kw < 3; ++kw) {
      const int pix0 = pb0 + kw, pix1 = pb1 + kw;
      const uint32_t bB0 = (uint32_t)(pix0 * 64 + chh * 16);
      const uint32_t bM0 = (uint32_t)((pix0 & 14) << 3);
      const uint32_t bB1 = (uint32_t)(pix1 * 64 + chh * 16);
      const uint32_t bM1 = (uint32_t)((pix1 & 14) << 3);
      const uint32_t kwq = (uint32_t)(kw * 8192);
#pragma unroll
      for (int kk = 0; kk < 2; ++kk) {
        const uint32_t kq = (uint32_t)(kk * 32);
        uint32_t a[4][4];
#pragma unroll
        for (int i = 0; i < 4; ++i) ldm4(a[i], stb + ST_A + ((aOff[i] + kwq + kq) ^ aMask[i]));
        uint32_t b0[4], b1[4];
        ldm4(b0, stb + ST_B + ((bB0 + kq) ^ bM0));
        ldm4(b1, stb + ST_B + ((bB1 + kq) ^ bM1));
#pragma unroll
        for (int i = 0; i < 4; ++i) {
          mma16816(acc[i][0], a[i], b0[0], b0[2]);
          mma16816(acc[i][1], a[i], b0[1], b0[3]);
          mma16816(acc[i][2], a[i], b1[0], b1[2]);
          mma16816(acc[i][3], a[i], b1[1], b1[3]);
        }
      }
    }
    __syncthreads();
  }

  // ---- epilogue: scale (EqualizedLR 1/48) + bias + direct float2 stores ----
  const float kS = 0.020833333333333332f;
  const int q = l >> 2, r2 = l & 3;
#pragma unroll
  for (int i = 0; i < 4; ++i) {
    const int ocA = oc0 + wm * 64 + i * 16 + q;
    const float bvA = bias[ocA];
    const float bvB = bias[ocA + 8];
    float* baseA = out + ((size_t)(n * C_OUT + ocA)) * 4096;
    float* baseB = baseA + (size_t)8 * 4096;
#pragma unroll
    for (int nn = 0; nn < 4; ++nn) {
      const int sp = wn * 32 + nn * 8 + 2 * r2;
      const int off = (oh0 + (sp >> 6)) * 64 + (sp & 63);
      float2 v0 = make_float2(acc[i][nn][0] * kS + bvA, acc[i][nn][1] * kS + bvA);
      float2 v1 = make_float2(acc[i][nn][2] * kS + bvB, acc[i][nn][3] * kS + bvB);
      *reinterpret_cast<float2*>(baseA + off) = v0;
      *reinterpret_cast<float2*>(baseB + off) = v1;
    }
  }
}

// ---------------------------------------------------------------------------
extern "C" void kernel_launch(void* const* d_in, const int* in_sizes, int n_in,
                              void* d_out, int out_size) {
  (void)in_sizes; (void)n_in; (void)out_size;
  const float* x    = (const float*)d_in[0];  // [16,256,128,128]
  const float* wgt  = (const float*)d_in[1];  // [512,256,3,3]
  const float* bias = (const float*)d_in[2];  // [512]
  const float* bk   = (const float*)d_in[3];  // [4,4]
  float* out = (float*)d_out;                 // [16,512,64,64]

  cudaFuncSetAttribute(conv_mma_kernel, cudaFuncAttributeMaxDynamicSharedMemorySize,
                       SMEM_BYTES);
  wsplit_kernel<<<(C_OUT * 9 * C_IN) / 256, 256>>>(wgt);
  blur_kernel<<<dim3(8, HB, N_IMG), 256>>>(x, bk);
  conv_mma_kernel<<<dim3(4, 512), 256, SMEM_BYTES>>>(bias, out);
}

// round 8
// speedup vs baseline: 8.0929x; 1.0304x over previous
#include <cuda_runtime.h>
#include <cuda_fp16.h>
#include <cstdint>

#define N_IMG 16
#define C_IN  256
#define H_IN  128
#define W_IN  128
#define HB    129
#define C_OUT 512

// ---- device scratch (allowed: __device__ globals) ----
__device__ __align__(256) __half g_act[(size_t)N_IMG * HB * HB * C_IN];  // fp16 activations (unscaled)
__device__ __align__(256) __half g_w[(size_t)C_OUT * 9 * C_IN];          // fp16 weights [oc][tap][ic]

// ---------------------------------------------------------------------------
// helpers (base sm_103-safe PTX only: ldmatrix / mma.sync / cp.async)
// ---------------------------------------------------------------------------
__device__ __forceinline__ uint32_t s2u(const void* p) {
  uint32_t a;
  asm("{ .reg .u64 t; cvta.to.shared.u64 t, %1; cvt.u32.u64 %0, t; }" : "=r"(a) : "l"(p));
  return a;
}
__device__ __forceinline__ void cpa16(uint32_t d, const void* s) {
  asm volatile("cp.async.cg.shared.global [%0], [%1], 16;" :: "r"(d), "l"(s));
}
__device__ __forceinline__ void cpa_commit() {
  asm volatile("cp.async.commit_group;" ::: "memory");
}
template <int N>
__device__ __forceinline__ void cpa_wait() {
  asm volatile("cp.async.wait_group %0;" :: "n"(N) : "memory");
}
__device__ __forceinline__ void ldm4(uint32_t* r, uint32_t addr) {
  asm volatile("ldmatrix.sync.aligned.m8n8.x4.shared.b16 {%0,%1,%2,%3}, [%4];"
               : "=r"(r[0]), "=r"(r[1]), "=r"(r[2]), "=r"(r[3]) : "r"(addr));
}
__device__ __forceinline__ void mma16816(float* d, const uint32_t* a,
                                         uint32_t b0, uint32_t b1) {
  asm volatile(
      "mma.sync.aligned.m16n8k16.row.col.f32.f16.f16.f32 "
      "{%0,%1,%2,%3}, {%4,%5,%6,%7}, {%8,%9}, {%0,%1,%2,%3};"
      : "+f"(d[0]), "+f"(d[1]), "+f"(d[2]), "+f"(d[3])
      : "r"(a[0]), "r"(a[1]), "r"(a[2]), "r"(a[3]), "r"(b0), "r"(b1));
}
__device__ __forceinline__ uint32_t swz(uint32_t x) { return x ^ ((x >> 3) & 0x70); }

// ---------------------------------------------------------------------------
// Kernel 1: weight cast.  w[oc][ic][kh][kw] fp32 -> w[oc][tap][ic] fp16
// ---------------------------------------------------------------------------
__global__ void __launch_bounds__(256) wsplit_kernel(const float* __restrict__ w) {
  const int idx = blockIdx.x * 256 + threadIdx.x;  // < 512*9*256 exactly
  const int oc = idx / (9 * C_IN);
  const int r = idx - oc * 9 * C_IN;
  const int tap = r >> 8;
  const int ic = r & 255;
  g_w[idx] = __float2half(w[(oc * C_IN + ic) * 9 + tap]);
}

// ---------------------------------------------------------------------------
// Kernel 2: separable 4x4 blur -> NHWC fp16 (single copy, unscaled).
// CTA = (icg of 32 ic, output row h, image n). 256 thr = 32 ic x 8 w-slices.
// ---------------------------------------------------------------------------
__global__ void __launch_bounds__(256) blur_kernel(const float* __restrict__ x,
                                                   const float* __restrict__ bk) {
  const int icg = blockIdx.x;   // 0..7
  const int h   = blockIdx.y;   // 0..128
  const int n   = blockIdx.z;   // 0..15
  const int t = threadIdx.x;
  const int ic_l = t & 31;
  const int ws = t >> 5;        // 0..7

  float vco[4], wco[4];
#pragma unroll
  for (int i = 0; i < 4; ++i) vco[i] = bk[i * 4] + bk[i * 4 + 1] + bk[i * 4 + 2] + bk[i * 4 + 3];
#pragma unroll
  for (int j = 0; j < 4; ++j) wco[j] = bk[j] + bk[4 + j] + bk[8 + j] + bk[12 + j];

  __shared__ __half sA[HB][32];

  const float* xp = x + (size_t)(n * C_IN + icg * 32 + ic_l) * (H_IN * W_IN);

  float4 v[6];
#pragma unroll
  for (int m = 0; m < 6; ++m) v[m] = make_float4(0.f, 0.f, 0.f, 0.f);
#pragma unroll
  for (int i = 0; i < 4; ++i) {
    const int r = h - 2 + i;
    if (r < 0 || r >= H_IN) continue;
    const float4* rp = reinterpret_cast<const float4*>(xp + r * W_IN);
    const float c = vco[i];
#pragma unroll
    for (int m = 0; m < 6; ++m) {
      const int c4 = ws * 4 - 1 + m;
      if (c4 >= 0 && c4 < 32) {
        const float4 d = rp[c4];
        v[m].x += c * d.x; v[m].y += c * d.y; v[m].z += c * d.z; v[m].w += c * d.w;
      }
    }
  }
  float vv[24];
#pragma unroll
  for (int m = 0; m < 6; ++m) {
    vv[4 * m] = v[m].x; vv[4 * m + 1] = v[m].y; vv[4 * m + 2] = v[m].z; vv[4 * m + 3] = v[m].w;
  }
#pragma unroll
  for (int k = 0; k < 17; ++k) {
    if (k == 16 && ws != 7) break;
    float s = wco[0] * vv[k + 2] + wco[1] * vv[k + 3] + wco[2] * vv[k + 4] + wco[3] * vv[k + 5];
    sA[ws * 16 + k][ic_l] = __float2half(s);
  }
  __syncthreads();

  const size_t base = ((size_t)(n * HB + h) * HB) * C_IN + icg * 32;
  for (int e = t; e < HB * 32; e += 256) {
    const int w = e >> 5, il = e & 31;
    g_act[base + (size_t)w * C_IN + il] = sA[w][il];
  }
}

// ---------------------------------------------------------------------------
// Kernel 3: mma.sync fp16 implicit GEMM, fat tiles.
// CTA: 128 oc x 256 spatial (4 out rows x 64 cols). 8 warps (2 M x 4 N),
// warp tile 64x64 (A frags reused across 8 N-blocks -> half the LDSM/FLOP).
// Stage = (ic-chunk of 32, kh): 4 input rows {2oh0+kh+2j} x 129 cols +
// weights for 3 kw taps. 24 stages, double-buffered (115.2KB), 1 CTA/SM.
// ---------------------------------------------------------------------------
#define ST_A 0
#define ST_B 24576
#define STAGE 57600
#define SMEM_BYTES (2 * STAGE)   // 115200

extern __shared__ char csm[];

__global__ void __launch_bounds__(256, 1) conv_mma_kernel(const float* __restrict__ bias,
                                                          float* __restrict__ out) {
  const int t = threadIdx.x;
  const int l = t & 31, w = t >> 5;
  const int wm = w >> 2, wn = w & 3;         // warp = 64 oc x (output row wn)
  const int ocg = blockIdx.x;                // 0..3
  const int by = blockIdx.y;                 // 0..255
  const int n = by >> 4, rg = by & 15;
  const int oh0 = rg * 4;
  const int oc0 = ocg * 128;
  const uint32_t sb = s2u(csm);

  // ---- staging precomputes (A only; B recomputed per stage to save regs) ----
  uint32_t a_sw[6], a_g[6];
#pragma unroll
  for (int k = 0; k < 6; ++k) {
    const int idx = t + k * 256;
    const int c = idx & 3, rowi = idx >> 2;
    const int kw = rowi >> 7, oc = rowi & 127;
    a_sw[k] = swz((uint32_t)(kw * 8192 + oc * 64 + c * 16));
    a_g[k] = (uint32_t)(((oc0 + oc) * 9 + kw) * C_IN + c * 8);  // + kh*768 + ic0
  }

  // ---- compute-side precomputes ----
  const int rl = l & 15, chh = l >> 4;
  uint32_t aOff[4], aMask[4];
#pragma unroll
  for (int i = 0; i < 4; ++i) {
    const int m = wm * 64 + i * 16 + rl;
    aOff[i] = (uint32_t)(m * 64 + chh * 16);
    aMask[i] = (uint32_t)((m & 14) << 3);
  }
  int pixB[4];
#pragma unroll
  for (int b = 0; b < 4; ++b) pixB[b] = wn * 129 + 32 * b + 2 * rl;

  float acc[4][8][4];
#pragma unroll
  for (int i = 0; i < 4; ++i)
#pragma unroll
    for (int j = 0; j < 8; ++j)
#pragma unroll
      for (int p = 0; p < 4; ++p) acc[i][j][p] = 0.f;

  auto stage = [&](int s) {
    const int chunk = s / 3, kh = s - chunk * 3;
    const int ic0 = chunk * 32;
    const uint32_t stb = sb + (uint32_t)(s & 1) * STAGE;
    const uint32_t aadd = (uint32_t)(kh * 3 * C_IN + ic0);
#pragma unroll
    for (int k = 0; k < 6; ++k) cpa16(stb + ST_A + a_sw[k], g_w + a_g[k] + aadd);
    // B: 2064 16B-chunks: idx -> c(0..3), pixel pp(0..515) = j*129 + colw
    const uint32_t brow0 = (uint32_t)((n * HB + 2 * oh0 + kh) * HB) * C_IN + ic0;
#pragma unroll
    for (int k = 0; k < 9; ++k) {
      const int idx = t + k * 256;
      if (k == 8 && t >= 16) break;
      const int c = idx & 3;
      const uint32_t pp = (uint32_t)(idx >> 2);
      const uint32_t j = pp / 129u;
      const uint32_t colw = pp - j * 129u;
      cpa16(stb + ST_B + swz(pp * 64 + c * 16),
            g_act + brow0 + (size_t)(2 * j * HB + colw) * C_IN + c * 8);
    }
    cpa_commit();
  };

  stage(0);

  for (int s = 0; s < 24; ++s) {
    if (s + 1 < 24) {
      stage(s + 1);
      cpa_wait<1>();
    } else {
      cpa_wait<0>();
    }
    __syncthreads();

    const uint32_t stb = sb + (uint32_t)(s & 1) * STAGE;
#pragma unroll
    for (int kw = 0; kw < 3; ++kw) {
      const uint32_t kwq = (uint32_t)(kw * 8192);
#pragma unroll
      for (int kk = 0; kk < 2; ++kk) {
        const uint32_t kq = (uint32_t)(kk * 32);
        uint32_t a[4][4];
#pragma unroll
        for (int i = 0; i < 4; ++i) ldm4(a[i], stb + ST_A + ((aOff[i] + kwq + kq) ^ aMask[i]));
        uint32_t bf[4][4];
#pragma unroll
        for (int b = 0; b < 4; ++b) {
          const int pix = pixB[b] + kw;
          const uint32_t bB = (uint32_t)(pix * 64 + chh * 16);
          const uint32_t bM = (uint32_t)((pix & 14) << 3);
          ldm4(bf[b], stb + ST_B + ((bB + kq) ^ bM));
        }
#pragma unroll
        for (int i = 0; i < 4; ++i)
#pragma unroll
          for (int b = 0; b < 4; ++b) {
            mma16816(acc[i][2 * b], a[i], bf[b][0], bf[b][2]);
            mma16816(acc[i][2 * b + 1], a[i], bf[b][1], bf[b][3]);
          }
      }
    }
    __syncthreads();
  }

  // ---- epilogue: scale (EqualizedLR 1/48) + bias + direct float2 stores ----
  const float kS = 0.020833333333333332f;
  const int q = l >> 2, r2 = l & 3;
#pragma unroll
  for (int i = 0; i < 4; ++i) {
    const int ocA = oc0 + wm * 64 + i * 16 + q;
    const float bvA = bias[ocA];
    const float bvB = bias[ocA + 8];
    float* baseA = out + ((size_t)(n * C_OUT + ocA)) * 4096 + (oh0 + wn) * 64;
    float* baseB = baseA + (size_t)8 * 4096;
#pragma unroll
    for (int jj = 0; jj < 8; ++jj) {
      const int col = jj * 8 + 2 * r2;
      float2 v0 = make_float2(acc[i][jj][0] * kS + bvA, acc[i][jj][1] * kS + bvA);
      float2 v1 = make_float2(acc[i][jj][2] * kS + bvB, acc[i][jj][3] * kS + bvB);
      *reinterpret_cast<float2*>(baseA + col) = v0;
      *reinterpret_cast<float2*>(baseB + col) = v1;
    }
  }
}

// ---------------------------------------------------------------------------
extern "C" void kernel_launch(void* const* d_in, const int* in_sizes, int n_in,
                              void* d_out, int out_size) {
  (void)in_sizes; (void)n_in; (void)out_size;
  const float* x    = (const float*)d_in[0];  // [16,256,128,128]
  const float* wgt  = (const float*)d_in[1];  // [512,256,3,3]
  const float* bias = (const float*)d_in[2];  // [512]
  const float* bk   = (const float*)d_in[3];  // [4,4]
  float* out = (float*)d_out;                 // [16,512,64,64]

  cudaFuncSetAttribute(conv_mma_kernel, cudaFuncAttributeMaxDynamicSharedMemorySize,
                       SMEM_BYTES);
  wsplit_kernel<<<(C_OUT * 9 * C_IN) / 256, 256>>>(wgt);
  blur_kernel<<<dim3(8, HB, N_IMG), 256>>>(x, bk);
  conv_mma_kernel<<<dim3(4, 256), 256, SMEM_BYTES>>>(bias, out);
}

// round 9
// speedup vs baseline: 8.2260x; 1.0164x over previous
#include <cuda_runtime.h>
#include <cuda_fp16.h>
#include <cstdint>

#define N_IMG 16
#define C_IN  256
#define H_IN  128
#define W_IN  128
#define HB    129
#define C_OUT 512

// ---- device scratch (allowed: __device__ globals) ----
__device__ __align__(256) __half g_act[(size_t)N_IMG * HB * HB * C_IN];  // fp16 activations (unscaled)
__device__ __align__(256) __half g_w[(size_t)C_OUT * 9 * C_IN];          // fp16 weights [oc][tap][ic]

// ---------------------------------------------------------------------------
// helpers (base sm_103-safe PTX only: ldmatrix / mma.sync / cp.async)
// ---------------------------------------------------------------------------
__device__ __forceinline__ uint32_t s2u(const void* p) {
  uint32_t a;
  asm("{ .reg .u64 t; cvta.to.shared.u64 t, %1; cvt.u32.u64 %0, t; }" : "=r"(a) : "l"(p));
  return a;
}
__device__ __forceinline__ void cpa16(uint32_t d, const void* s) {
  asm volatile("cp.async.cg.shared.global [%0], [%1], 16;" :: "r"(d), "l"(s));
}
__device__ __forceinline__ void cpa_commit() {
  asm volatile("cp.async.commit_group;" ::: "memory");
}
template <int N>
__device__ __forceinline__ void cpa_wait() {
  asm volatile("cp.async.wait_group %0;" :: "n"(N) : "memory");
}
__device__ __forceinline__ void ldm4(uint32_t* r, uint32_t addr) {
  asm volatile("ldmatrix.sync.aligned.m8n8.x4.shared.b16 {%0,%1,%2,%3}, [%4];"
               : "=r"(r[0]), "=r"(r[1]), "=r"(r[2]), "=r"(r[3]) : "r"(addr));
}
__device__ __forceinline__ void mma16816(float* d, const uint32_t* a,
                                         uint32_t b0, uint32_t b1) {
  asm volatile(
      "mma.sync.aligned.m16n8k16.row.col.f32.f16.f16.f32 "
      "{%0,%1,%2,%3}, {%4,%5,%6,%7}, {%8,%9}, {%0,%1,%2,%3};"
      : "+f"(d[0]), "+f"(d[1]), "+f"(d[2]), "+f"(d[3])
      : "r"(a[0]), "r"(a[1]), "r"(a[2]), "r"(a[3]), "r"(b0), "r"(b1));
}
__device__ __forceinline__ uint32_t swz(uint32_t x) { return x ^ ((x >> 3) & 0x70); }

// ---------------------------------------------------------------------------
// Kernel 1: weight cast.  w[oc][ic][kh][kw] fp32 -> w[oc][tap][ic] fp16
// ---------------------------------------------------------------------------
__global__ void __launch_bounds__(256) wsplit_kernel(const float* __restrict__ w) {
  const int idx = blockIdx.x * 256 + threadIdx.x;  // < 512*9*256 exactly
  const int oc = idx / (9 * C_IN);
  const int r = idx - oc * 9 * C_IN;
  const int tap = r >> 8;
  const int ic = r & 255;
  g_w[idx] = __float2half(w[(oc * C_IN + ic) * 9 + tap]);
}

// ---------------------------------------------------------------------------
// Kernel 2: separable 4x4 blur -> NHWC fp16 (single copy, unscaled).
// CTA = (icg of 32 ic, output row h, image n). 256 thr = 32 ic x 8 w-slices.
// ---------------------------------------------------------------------------
__global__ void __launch_bounds__(256) blur_kernel(const float* __restrict__ x,
                                                   const float* __restrict__ bk) {
  const int icg = blockIdx.x;   // 0..7
  const int h   = blockIdx.y;   // 0..128
  const int n   = blockIdx.z;   // 0..15
  const int t = threadIdx.x;
  const int ic_l = t & 31;
  const int ws = t >> 5;        // 0..7

  float vco[4], wco[4];
#pragma unroll
  for (int i = 0; i < 4; ++i) vco[i] = bk[i * 4] + bk[i * 4 + 1] + bk[i * 4 + 2] + bk[i * 4 + 3];
#pragma unroll
  for (int j = 0; j < 4; ++j) wco[j] = bk[j] + bk[4 + j] + bk[8 + j] + bk[12 + j];

  __shared__ __half sA[HB][32];

  const float* xp = x + (size_t)(n * C_IN + icg * 32 + ic_l) * (H_IN * W_IN);

  float4 v[6];
#pragma unroll
  for (int m = 0; m < 6; ++m) v[m] = make_float4(0.f, 0.f, 0.f, 0.f);
#pragma unroll
  for (int i = 0; i < 4; ++i) {
    const int r = h - 2 + i;
    if (r < 0 || r >= H_IN) continue;
    const float4* rp = reinterpret_cast<const float4*>(xp + r * W_IN);
    const float c = vco[i];
#pragma unroll
    for (int m = 0; m < 6; ++m) {
      const int c4 = ws * 4 - 1 + m;
      if (c4 >= 0 && c4 < 32) {
        const float4 d = rp[c4];
        v[m].x += c * d.x; v[m].y += c * d.y; v[m].z += c * d.z; v[m].w += c * d.w;
      }
    }
  }
  float vv[24];
#pragma unroll
  for (int m = 0; m < 6; ++m) {
    vv[4 * m] = v[m].x; vv[4 * m + 1] = v[m].y; vv[4 * m + 2] = v[m].z; vv[4 * m + 3] = v[m].w;
  }
#pragma unroll
  for (int k = 0; k < 17; ++k) {
    if (k == 16 && ws != 7) break;
    float s = wco[0] * vv[k + 2] + wco[1] * vv[k + 3] + wco[2] * vv[k + 4] + wco[3] * vv[k + 5];
    sA[ws * 16 + k][ic_l] = __float2half(s);
  }
  __syncthreads();

  const size_t base = ((size_t)(n * HB + h) * HB) * C_IN + icg * 32;
  for (int e = t; e < HB * 32; e += 256) {
    const int w = e >> 5, il = e & 31;
    g_act[base + (size_t)w * C_IN + il] = sA[w][il];
  }
}

// ---------------------------------------------------------------------------
// Kernel 3: mma.sync fp16 implicit GEMM, fat tiles, 3-stage pipeline.
// CTA: 128 oc x 256 spatial (4 out rows x 64 cols). 8 warps (2 M x 4 N),
// warp tile 64x64. Stage = (ic-chunk of 32, kh): 4 input rows + 3 kw weight
// tiles. 24 stages, TRIPLE-buffered, prefetch distance 2, ONE barrier/stage
// (sync-first ordering makes the overwrite hazard cross the barrier).
// ---------------------------------------------------------------------------
#define ST_A 0
#define ST_B 24576
#define STAGE 57600
#define SMEM_BYTES (3 * STAGE)   // 172800

extern __shared__ char csm[];

__global__ void __launch_bounds__(256, 1) conv_mma_kernel(const float* __restrict__ bias,
                                                          float* __restrict__ out) {
  const int t = threadIdx.x;
  const int l = t & 31, w = t >> 5;
  const int wm = w >> 2, wn = w & 3;         // warp = 64 oc x (output row wn)
  const int ocg = blockIdx.x;                // 0..3
  const int by = blockIdx.y;                 // 0..255
  const int n = by >> 4, rg = by & 15;
  const int oh0 = rg * 4;
  const int oc0 = ocg * 128;
  const uint32_t sb = s2u(csm);

  // ---- staging precomputes ----
  uint32_t a_sw[6], a_g[6];
#pragma unroll
  for (int k = 0; k < 6; ++k) {
    const int idx = t + k * 256;
    const int c = idx & 3, rowi = idx >> 2;
    const int kw = rowi >> 7, oc = rowi & 127;
    a_sw[k] = swz((uint32_t)(kw * 8192 + oc * 64 + c * 16));
    a_g[k] = (uint32_t)(((oc0 + oc) * 9 + kw) * C_IN + c * 8);  // + kh*768 + ic0
  }
  // B: 2064 16B-chunks: idx -> c(0..3), pixel pp(0..515) = j*129 + colw
  uint32_t b_sw[9], b_g[9];
#pragma unroll
  for (int k = 0; k < 9; ++k) {
    const int idx = t + k * 256;
    const int c = idx & 3;
    const uint32_t pp = (uint32_t)(idx >> 2);
    const uint32_t j = pp / 129u;
    const uint32_t colw = pp - j * 129u;
    b_sw[k] = swz(pp * 64 + c * 16);
    b_g[k] = (2 * j * HB + colw) * C_IN + c * 8;   // + brow0 at use
  }

  // ---- compute-side precomputes ----
  const int rl = l & 15, chh = l >> 4;
  uint32_t aOff[4], aMask[4];
#pragma unroll
  for (int i = 0; i < 4; ++i) {
    const int m = wm * 64 + i * 16 + rl;
    aOff[i] = (uint32_t)(m * 64 + chh * 16);
    aMask[i] = (uint32_t)((m & 14) << 3);
  }
  int pixB[4];
#pragma unroll
  for (int b = 0; b < 4; ++b) pixB[b] = wn * 129 + 32 * b + 2 * rl;

  float acc[4][8][4];
#pragma unroll
  for (int i = 0; i < 4; ++i)
#pragma unroll
    for (int j = 0; j < 8; ++j)
#pragma unroll
      for (int p = 0; p < 4; ++p) acc[i][j][p] = 0.f;

  auto stage = [&](int s) {
    const int chunk = s / 3, kh = s - chunk * 3;
    const int ic0 = chunk * 32;
    const uint32_t stb = sb + (uint32_t)(s % 3) * STAGE;
    const uint32_t aadd = (uint32_t)(kh * 3 * C_IN + ic0);
    const uint32_t brow0 = (uint32_t)((n * HB + 2 * oh0 + kh) * HB) * C_IN + ic0;
#pragma unroll
    for (int k = 0; k < 6; ++k) cpa16(stb + ST_A + a_sw[k], g_w + a_g[k] + aadd);
#pragma unroll
    for (int k = 0; k < 9; ++k) {
      if (k < 8 || t < 16) cpa16(stb + ST_B + b_sw[k], g_act + brow0 + b_g[k]);
    }
    cpa_commit();
  };

  stage(0);
  stage(1);

  for (int s = 0; s < 24; ++s) {
    __syncthreads();                 // all warps done with buf[(s-1)%3] == buf[(s+2)%3]
    if (s + 2 < 24) {
      stage(s + 2);
      cpa_wait<2>();                 // stage s complete (s+1, s+2 may be pending)
    } else if (s + 1 < 24) {
      cpa_wait<1>();
    } else {
      cpa_wait<0>();
    }

    const uint32_t stb = sb + (uint32_t)(s % 3) * STAGE;
#pragma unroll
    for (int kw = 0; kw < 3; ++kw) {
      const uint32_t kwq = (uint32_t)(kw * 8192);
#pragma unroll
      for (int kk = 0; kk < 2; ++kk) {
        const uint32_t kq = (uint32_t)(kk * 32);
        uint32_t a[4][4];
#pragma unroll
        for (int i = 0; i < 4; ++i) ldm4(a[i], stb + ST_A + ((aOff[i] + kwq + kq) ^ aMask[i]));
        uint32_t bf[4][4];
#pragma unroll
        for (int b = 0; b < 4; ++b) {
          const int pix = pixB[b] + kw;
          const uint32_t bB = (uint32_t)(pix * 64 + chh * 16);
          const uint32_t bM = (uint32_t)((pix & 14) << 3);
          ldm4(bf[b], stb + ST_B + ((bB + kq) ^ bM));
        }
#pragma unroll
        for (int i = 0; i < 4; ++i)
#pragma unroll
          for (int b = 0; b < 4; ++b) {
            mma16816(acc[i][2 * b], a[i], bf[b][0], bf[b][2]);
            mma16816(acc[i][2 * b + 1], a[i], bf[b][1], bf[b][3]);
          }
      }
    }
  }

  // ---- epilogue: scale (EqualizedLR 1/48) + bias + direct float2 stores ----
  const float kS = 0.020833333333333332f;
  const int q = l >> 2, r2 = l & 3;
#pragma unroll
  for (int i = 0; i < 4; ++i) {
    const int ocA = oc0 + wm * 64 + i * 16 + q;
    const float bvA = bias[ocA];
    const float bvB = bias[ocA + 8];
    float* baseA = out + ((size_t)(n * C_OUT + ocA)) * 4096 + (oh0 + wn) * 64;
    float* baseB = baseA + (size_t)8 * 4096;
#pragma unroll
    for (int jj = 0; jj < 8; ++jj) {
      const int col = jj * 8 + 2 * r2;
      float2 v0 = make_float2(acc[i][jj][0] * kS + bvA, acc[i][jj][1] * kS + bvA);
      float2 v1 = make_float2(acc[i][jj][2] * kS + bvB, acc[i][jj][3] * kS + bvB);
      *reinterpret_cast<float2*>(baseA + col) = v0;
      *reinterpret_cast<float2*>(baseB + col) = v1;
    }
  }
}

// ---------------------------------------------------------------------------
extern "C" void kernel_launch(void* const* d_in, const int* in_sizes, int n_in,
                              void* d_out, int out_size) {
  (void)in_sizes; (void)n_in; (void)out_size;
  const float* x    = (const float*)d_in[0];  // [16,256,128,128]
  const float* wgt  = (const float*)d_in[1];  // [512,256,3,3]
  const float* bias = (const float*)d_in[2];  // [512]
  const float* bk   = (const float*)d_in[3];  // [4,4]
  float* out = (float*)d_out;                 // [16,512,64,64]

  cudaFuncSetAttribute(conv_mma_kernel, cudaFuncAttributeMaxDynamicSharedMemorySize,
                       SMEM_BYTES);
  wsplit_kernel<<<(C_OUT * 9 * C_IN) / 256, 256>>>(wgt);
  blur_kernel<<<dim3(8, HB, N_IMG), 256>>>(x, bk);
  conv_mma_kernel<<<dim3(4, 256), 256, SMEM_BYTES>>>(bias, out);
}